// round 15
// baseline (speedup 1.0000x reference)
#include <cuda_runtime.h>
#include <cstdint>
#include <cstdio>

#define BB 4
#define TT 12
#define NNODE 2000
#define NEDGE 32000
#define NDIM 16
#define EDIM 8
#define NH 4
#define DD 16
#define GG 64
#define GHH 64
#define BT 48   // BB*TT

// ---------------- scratch (device globals) ----------------
static __device__ float    g_sd  [(size_t)BT*NNODE*NH];
static __device__ float    g_ss  [(size_t)BT*NNODE*NH];
static __device__ float    g_score[(size_t)BT*NEDGE*NH];    // ALPHA
static __device__ float    g_gin [(size_t)BB*NNODE*TT*GG];  // LN out, row=(b*N+n)*T+t
static __device__ float    g_gi  [(size_t)BB*NNODE*TT*3*GHH];
static __device__ float    g_Md[NDIM*NH], g_Ms[NDIM*NH], g_Me[EDIM*NH];
static __device__ int      g_src[NEDGE], g_dst[NEDGE];
static __device__ int      g_deg[NNODE];                    // zero at entry (re-zeroed by scan)
static __device__ int      g_cur[NNODE];
static __device__ int      g_off[NNODE+1], g_csr[NEDGE];

// ---------------- csr 1: copy edge list + count degrees ----------------
__global__ void k_count(const int* __restrict__ ei) {
    int e = blockIdx.x * blockDim.x + threadIdx.x;
    if (e < NEDGE) {
        int s = ei[e], d = ei[NEDGE + e];
        g_src[e] = s; g_dst[e] = d;
        atomicAdd(&g_deg[d], 1);
    }
}

// ---------------- csr 2: scan + re-zero g_deg ----------------
__global__ void k_scan() {
    __shared__ int sa[2048], sb[2048];
    int tid = threadIdx.x;                 // 1024
    for (int i = tid; i < 2048; i += 1024) {
        sa[i] = (i < NNODE) ? g_deg[i] : 0;
        if (i < NNODE) g_deg[i] = 0;       // restore invariant for graph replay
    }
    __syncthreads();
    int* cur = sa; int* nxt = sb;
    for (int d = 1; d < 2048; d <<= 1) {
        for (int i = tid; i < 2048; i += 1024)
            nxt[i] = (i >= d) ? cur[i] + cur[i - d] : cur[i];
        __syncthreads();
        int* t = cur; cur = nxt; nxt = t;
    }
    for (int i = tid; i < NNODE; i += 1024) {
        int off = (i == 0) ? 0 : cur[i - 1];
        g_off[i] = off;
        g_cur[i] = off;
    }
    if (tid == 0) g_off[NNODE] = cur[NNODE - 1];
}

// ---------------- csr 3: atomic fill ----------------
__global__ void k_fillA() {
    int e = blockIdx.x * blockDim.x + threadIdx.x;
    if (e < NEDGE) {
        int pos = atomicAdd(&g_cur[g_dst[e]], 1);
        g_csr[pos] = e;
    }
}

// ---------------- csr 4: warp-per-node bitonic sort ----------------
__global__ void k_sortB() {
    int gw   = (blockIdx.x * blockDim.x + threadIdx.x) >> 5;
    int lane = threadIdx.x & 31;
    if (gw >= NNODE) return;
    int off = g_off[gw];
    int deg = g_off[gw + 1] - off;
    if (deg <= 1) return;
    if (deg <= 32) {
        int v = (lane < deg) ? g_csr[off + lane] : 0x7FFFFFFF;
        #pragma unroll
        for (int k = 2; k <= 32; k <<= 1) {
            #pragma unroll
            for (int j = k >> 1; j > 0; j >>= 1) {
                int o = __shfl_xor_sync(0xFFFFFFFFu, v, j);
                bool lower = (lane & j) == 0;
                bool asc   = (lane & k) == 0;
                v = (lower == asc) ? min(v, o) : max(v, o);
            }
        }
        if (lane < deg) g_csr[off + lane] = v;
    } else if (lane == 0) {
        for (int i = 1; i < deg; i++) {
            int v = g_csr[off + i], k = i - 1;
            while (k >= 0 && g_csr[off + k] > v) { g_csr[off + k + 1] = g_csr[off + k]; k--; }
            g_csr[off + k + 1] = v;
        }
    }
}

// ---------------- prep: fold att vectors into tiny matrices (side stream) ----------
__global__ void k_prep(const float* __restrict__ Wn, const float* __restrict__ We,
                       const float* __restrict__ att) {
    int tid = threadIdx.x;
    if (tid < NDIM*NH) {
        int c = tid >> 2, h = tid & 3;
        float s0 = 0.f, s1 = 0.f;
        #pragma unroll
        for (int d = 0; d < DD; d++) {
            float w = Wn[c*GG + h*DD + d];
            s0 += w * att[h*(3*DD) + d];
            s1 += w * att[h*(3*DD) + DD + d];
        }
        g_Md[c*NH + h] = s0;
        g_Ms[c*NH + h] = s1;
    } else if (tid < NDIM*NH + EDIM*NH) {
        int k = tid - NDIM*NH;
        int c = k >> 2, h = k & 3;
        float s = 0.f;
        #pragma unroll
        for (int d = 0; d < DD; d++)
            s += We[c*GG + h*DD + d] * att[h*(3*DD) + 2*DD + d];
        g_Me[c*NH + h] = s;
    }
}

// ---------------- node score terms: sd/ss = x @ Md / Ms ----------------
__global__ void k_node(const float* __restrict__ xf) {
    int gn = blockIdx.x * blockDim.x + threadIdx.x;   // [0, BT*NNODE)
    if (gn >= BT*NNODE) return;
    const float* xp = xf + (size_t)gn * NDIM;
    float x[NDIM];
    #pragma unroll
    for (int c = 0; c < NDIM; c += 4) {
        float4 v = *reinterpret_cast<const float4*>(xp + c);
        x[c] = v.x; x[c+1] = v.y; x[c+2] = v.z; x[c+3] = v.w;
    }
    float sd[NH] = {0.f,0.f,0.f,0.f}, ss[NH] = {0.f,0.f,0.f,0.f};
    #pragma unroll
    for (int c = 0; c < NDIM; c++) {
        float4 md = *reinterpret_cast<const float4*>(&g_Md[c*NH]);
        float4 ms = *reinterpret_cast<const float4*>(&g_Ms[c*NH]);
        sd[0] = fmaf(x[c], md.x, sd[0]); sd[1] = fmaf(x[c], md.y, sd[1]);
        sd[2] = fmaf(x[c], md.z, sd[2]); sd[3] = fmaf(x[c], md.w, sd[3]);
        ss[0] = fmaf(x[c], ms.x, ss[0]); ss[1] = fmaf(x[c], ms.y, ss[1]);
        ss[2] = fmaf(x[c], ms.z, ss[2]); ss[3] = fmaf(x[c], ms.w, ss[3]);
    }
    *reinterpret_cast<float4*>(&g_sd[(size_t)gn*NH]) = make_float4(sd[0], sd[1], sd[2], sd[3]);
    *reinterpret_cast<float4*>(&g_ss[(size_t)gn*NH]) = make_float4(ss[0], ss[1], ss[2], ss[3]);
}

// ---------------- k_gat: per-batch (12 graphs); fused softmax + agg + proj + LN ------
__global__ void __launch_bounds__(256) k_gat(const float* __restrict__ xf,
                                             const float* __restrict__ efeat,
                                             const float* __restrict__ Wn,
                                             const float* __restrict__ We,
                                             const float* __restrict__ gamma,
                                             const float* __restrict__ beta,
                                             int gbase) {
    __shared__ float s_al [8][32*4];
    __shared__ float s_ef [8][32*8];
    __shared__ int   s_src[8][32];
    __shared__ float s_axs[8][64];
    __shared__ float s_aef[8][32];

    int g    = gbase + blockIdx.y;
    int warp = threadIdx.x >> 5;
    int lane = threadIdx.x & 31;
    int node = blockIdx.x * 8 + warp;
    unsigned gE = (unsigned)g * NEDGE;
    unsigned gN = (unsigned)g * NNODE;
    const float* xg = xf + (size_t)gN * NDIM;
    const float* eg = efeat + (size_t)gE * EDIM;

    int off = g_off[node];
    int deg = g_off[node + 1] - off;
    float4 sd4 = *reinterpret_cast<const float4*>(&g_sd[(size_t)(gN + node)*NH]);

    int hA  = lane >> 4;
    int cA  = lane & 15;
    int hM  = lane >> 3;
    int cM  = lane & 7;
    float axs0 = 0.f, axs1 = 0.f, aef = 0.f;

    if (deg <= 32) {
        bool v = lane < deg;
        int e = 0, src = 0;
        float4 ea = make_float4(0.f,0.f,0.f,0.f), eb = ea, ss4 = ea;
        if (v) {
            e = g_csr[off + lane];
            src = g_src[e];
            const float* ef = eg + e*EDIM;
            ea = *reinterpret_cast<const float4*>(ef);
            eb = *reinterpret_cast<const float4*>(ef + 4);
            ss4 = *reinterpret_cast<const float4*>(&g_ss[(size_t)(gN + src)*NH]);
        }
        float efv[8] = {ea.x, ea.y, ea.z, ea.w, eb.x, eb.y, eb.z, eb.w};
        float s0 = sd4.x + ss4.x, s1 = sd4.y + ss4.y;
        float s2 = sd4.z + ss4.z, s3 = sd4.w + ss4.w;
        #pragma unroll
        for (int c = 0; c < EDIM; c++) {
            float4 me = *reinterpret_cast<const float4*>(&g_Me[c*NH]);
            s0 = fmaf(efv[c], me.x, s0);
            s1 = fmaf(efv[c], me.y, s1);
            s2 = fmaf(efv[c], me.z, s2);
            s3 = fmaf(efv[c], me.w, s3);
        }
        s0 = (s0 > 0.f) ? s0 : 0.2f*s0;  s1 = (s1 > 0.f) ? s1 : 0.2f*s1;
        s2 = (s2 > 0.f) ? s2 : 0.2f*s2;  s3 = (s3 > 0.f) ? s3 : 0.2f*s3;
        if (!v) { s0 = s1 = s2 = s3 = -1e30f; }
        float m0 = s0, m1 = s1, m2 = s2, m3 = s3;
        #pragma unroll
        for (int o = 16; o; o >>= 1) {
            m0 = fmaxf(m0, __shfl_xor_sync(0xFFFFFFFFu, m0, o));
            m1 = fmaxf(m1, __shfl_xor_sync(0xFFFFFFFFu, m1, o));
            m2 = fmaxf(m2, __shfl_xor_sync(0xFFFFFFFFu, m2, o));
            m3 = fmaxf(m3, __shfl_xor_sync(0xFFFFFFFFu, m3, o));
        }
        float e0 = v ? __expf(s0 - m0) : 0.f;
        float e1 = v ? __expf(s1 - m1) : 0.f;
        float e2 = v ? __expf(s2 - m2) : 0.f;
        float e3 = v ? __expf(s3 - m3) : 0.f;
        float t0 = e0, t1 = e1, t2 = e2, t3 = e3;
        #pragma unroll
        for (int o = 16; o; o >>= 1) {
            t0 += __shfl_xor_sync(0xFFFFFFFFu, t0, o);
            t1 += __shfl_xor_sync(0xFFFFFFFFu, t1, o);
            t2 += __shfl_xor_sync(0xFFFFFFFFu, t2, o);
            t3 += __shfl_xor_sync(0xFFFFFFFFu, t3, o);
        }
        if (v) {
            float4 al = make_float4(e0/(t0 + 1e-16f), e1/(t1 + 1e-16f),
                                    e2/(t2 + 1e-16f), e3/(t3 + 1e-16f));
            *reinterpret_cast<float4*>(&g_score[(size_t)(gE + e)*NH]) = al;
            s_src[warp][lane] = src;
            *reinterpret_cast<float4*>(&s_al[warp][lane*4]) = al;
            *reinterpret_cast<float4*>(&s_ef[warp][lane*8])     = ea;
            *reinterpret_cast<float4*>(&s_ef[warp][lane*8 + 4]) = eb;
        }
        __syncwarp();
        for (int i = 0; i < deg; i++) {
            int s = s_src[warp][i];
            float a_lo = s_al[warp][i*4 + hA];
            float a_hi = s_al[warp][i*4 + 2 + hA];
            float xv = __ldg(&xg[s*NDIM + cA]);
            axs0 = fmaf(a_lo, xv, axs0);
            axs1 = fmaf(a_hi, xv, axs1);
            aef  = fmaf(s_al[warp][i*4 + hM], s_ef[warp][i*8 + cM], aef);
        }
    } else {
        float m0 = -1e30f, m1 = -1e30f, m2 = -1e30f, m3 = -1e30f;
        for (int i = lane; i < deg; i += 32) {
            int e = g_csr[off + i];
            const float* ef = eg + e*EDIM;
            float4 ea = *reinterpret_cast<const float4*>(ef);
            float4 eb = *reinterpret_cast<const float4*>(ef + 4);
            float efv[8] = {ea.x, ea.y, ea.z, ea.w, eb.x, eb.y, eb.z, eb.w};
            float4 ss4 = *reinterpret_cast<const float4*>(&g_ss[(size_t)(gN + g_src[e])*NH]);
            float s0 = sd4.x + ss4.x, s1 = sd4.y + ss4.y;
            float s2 = sd4.z + ss4.z, s3 = sd4.w + ss4.w;
            #pragma unroll
            for (int c = 0; c < EDIM; c++) {
                float4 me = *reinterpret_cast<const float4*>(&g_Me[c*NH]);
                s0 = fmaf(efv[c], me.x, s0);
                s1 = fmaf(efv[c], me.y, s1);
                s2 = fmaf(efv[c], me.z, s2);
                s3 = fmaf(efv[c], me.w, s3);
            }
            s0 = (s0 > 0.f) ? s0 : 0.2f*s0;  s1 = (s1 > 0.f) ? s1 : 0.2f*s1;
            s2 = (s2 > 0.f) ? s2 : 0.2f*s2;  s3 = (s3 > 0.f) ? s3 : 0.2f*s3;
            *reinterpret_cast<float4*>(&g_score[(size_t)(gE + e)*NH]) = make_float4(s0, s1, s2, s3);
            m0 = fmaxf(m0, s0); m1 = fmaxf(m1, s1);
            m2 = fmaxf(m2, s2); m3 = fmaxf(m3, s3);
        }
        #pragma unroll
        for (int o = 16; o; o >>= 1) {
            m0 = fmaxf(m0, __shfl_xor_sync(0xFFFFFFFFu, m0, o));
            m1 = fmaxf(m1, __shfl_xor_sync(0xFFFFFFFFu, m1, o));
            m2 = fmaxf(m2, __shfl_xor_sync(0xFFFFFFFFu, m2, o));
            m3 = fmaxf(m3, __shfl_xor_sync(0xFFFFFFFFu, m3, o));
        }
        float t0 = 0.f, t1 = 0.f, t2 = 0.f, t3 = 0.f;
        for (int i = lane; i < deg; i += 32) {
            int e = g_csr[off + i];
            float4 sc = *reinterpret_cast<const float4*>(&g_score[(size_t)(gE + e)*NH]);
            float e0 = __expf(sc.x - m0), e1 = __expf(sc.y - m1);
            float e2 = __expf(sc.z - m2), e3 = __expf(sc.w - m3);
            *reinterpret_cast<float4*>(&g_score[(size_t)(gE + e)*NH]) = make_float4(e0, e1, e2, e3);
            t0 += e0; t1 += e1; t2 += e2; t3 += e3;
        }
        #pragma unroll
        for (int o = 16; o; o >>= 1) {
            t0 += __shfl_xor_sync(0xFFFFFFFFu, t0, o);
            t1 += __shfl_xor_sync(0xFFFFFFFFu, t1, o);
            t2 += __shfl_xor_sync(0xFFFFFFFFu, t2, o);
            t3 += __shfl_xor_sync(0xFFFFFFFFu, t3, o);
        }
        float r0 = 1.f/(t0 + 1e-16f), r1 = 1.f/(t1 + 1e-16f);
        float r2 = 1.f/(t2 + 1e-16f), r3 = 1.f/(t3 + 1e-16f);
        for (int i = lane; i < deg; i += 32) {
            int e = g_csr[off + i];
            float4 es = *reinterpret_cast<const float4*>(&g_score[(size_t)(gE + e)*NH]);
            *reinterpret_cast<float4*>(&g_score[(size_t)(gE + e)*NH]) =
                make_float4(es.x*r0, es.y*r1, es.z*r2, es.w*r3);
        }
        __threadfence();
        __syncwarp();
        for (int i = 0; i < deg; i++) {
            int e = g_csr[off + i];
            int s = __ldg(&g_src[e]);
            const float* ap = &g_score[(size_t)(gE + e)*NH];
            float a_lo = __ldg(ap + hA);
            float a_hi = __ldg(ap + 2 + hA);
            float a_me = __ldg(ap + hM);
            float xv   = __ldg(&xg[s*NDIM + cA]);
            float ev   = __ldg(&eg[e*EDIM + cM]);
            axs0 = fmaf(a_lo, xv, axs0);
            axs1 = fmaf(a_hi, xv, axs1);
            aef  = fmaf(a_me, ev, aef);
        }
    }

    s_axs[warp][hA*16 + cA]       = axs0;
    s_axs[warp][(2 + hA)*16 + cA] = axs1;
    s_aef[warp][lane] = aef;
    __syncwarp();

    float o01[2];
    #pragma unroll
    for (int half = 0; half < 2; half++) {
        int j = lane + half*32;
        int h = j >> 4;
        float acc = 0.f;
        #pragma unroll
        for (int c = 0; c < NDIM; c++)
            acc = fmaf(s_axs[warp][h*16 + c], __ldg(&Wn[c*GG + j]), acc);
        #pragma unroll
        for (int c = 0; c < EDIM; c++)
            acc = fmaf(s_aef[warp][h*8 + c], __ldg(&We[c*GG + j]), acc);
        o01[half] = (acc > 0.f) ? acc : (__expf(acc) - 1.f);
    }
    float s = o01[0] + o01[1];
    float q = o01[0]*o01[0] + o01[1]*o01[1];
    #pragma unroll
    for (int o = 16; o; o >>= 1) {
        s += __shfl_xor_sync(0xFFFFFFFFu, s, o);
        q += __shfl_xor_sync(0xFFFFFFFFu, q, o);
    }
    float mu = s * (1.f/GG);
    float inv = rsqrtf(q * (1.f/GG) - mu*mu + 1e-5f);
    int b = g / TT, t = g - b*TT;
    size_t gb = (((size_t)b*NNODE + node)*TT + t)*GG;
    g_gin[gb + lane]      = (o01[0] - mu)*inv*__ldg(&gamma[lane])      + __ldg(&beta[lane]);
    g_gin[gb + lane + 32] = (o01[1] - mu)*inv*__ldg(&gamma[lane + 32]) + __ldg(&beta[lane + 32]);
}

// ---------------- attention output ----------------
__global__ void k_attn(float* __restrict__ out3) {
    int te = blockIdx.x * blockDim.x + threadIdx.x;
    if (te >= TT*NEDGE) return;
    int e = te % NEDGE;
    int t = te / NEDGE;
    float4 s = make_float4(0.f, 0.f, 0.f, 0.f);
    #pragma unroll
    for (int b = 0; b < BB; b++) {
        float4 v = *reinterpret_cast<const float4*>(
            &g_score[(((size_t)(b*TT + t))*NEDGE + e)*NH]);
        s.x += v.x; s.y += v.y; s.z += v.z; s.w += v.w;
    }
    s.x *= 0.25f; s.y *= 0.25f; s.z *= 0.25f; s.w *= 0.25f;
    *reinterpret_cast<float4*>(&out3[(size_t)te*NH]) = s;
}

// ---------------- gi GEMM: per-batch; gate-split 64x64, 4r x 4c/thread ---------------
__global__ void __launch_bounds__(256) k_gi(const float* __restrict__ Wih,
                                            const float* __restrict__ bih,
                                            int rowbase) {
    __shared__ float Ws[64*64];      // Ws[k*64+o]
    __shared__ float X [64*68];      // X[r*68+k]
    int tid = threadIdx.x;
    int sgate = blockIdx.y;          // 0..2
    for (int i = tid; i < 64*64; i += 256) {
        int o = i >> 6, k = i & 63;
        Ws[k*64 + o] = Wih[(size_t)(sgate*64 + o)*64 + k];
    }
    size_t row0 = (size_t)rowbase + (size_t)blockIdx.x * 64;
    for (int i = tid; i < 64*64; i += 256) {
        int r = i >> 6, k = i & 63;
        X[r*68 + k] = g_gin[row0*GG + i];
    }
    __syncthreads();
    int tx = tid & 15;               // cols tx*4..+4
    int ty = tid >> 4;               // rows ty*4..+4
    float acc[4][4];
    #pragma unroll
    for (int r = 0; r < 4; r++)
        #pragma unroll
        for (int c = 0; c < 4; c++) acc[r][c] = 0.f;
    #pragma unroll 4
    for (int k = 0; k < 64; k += 4) {
        float4 w0 = *reinterpret_cast<float4*>(&Ws[(k+0)*64 + tx*4]);
        float4 w1 = *reinterpret_cast<float4*>(&Ws[(k+1)*64 + tx*4]);
        float4 w2 = *reinterpret_cast<float4*>(&Ws[(k+2)*64 + tx*4]);
        float4 w3 = *reinterpret_cast<float4*>(&Ws[(k+3)*64 + tx*4]);
        #pragma unroll
        for (int r = 0; r < 4; r++) {
            float4 xv = *reinterpret_cast<float4*>(&X[(ty*4 + r)*68 + k]);
            acc[r][0] = fmaf(xv.x, w0.x, acc[r][0]);
            acc[r][1] = fmaf(xv.x, w0.y, acc[r][1]);
            acc[r][2] = fmaf(xv.x, w0.z, acc[r][2]);
            acc[r][3] = fmaf(xv.x, w0.w, acc[r][3]);
            acc[r][0] = fmaf(xv.y, w1.x, acc[r][0]);
            acc[r][1] = fmaf(xv.y, w1.y, acc[r][1]);
            acc[r][2] = fmaf(xv.y, w1.z, acc[r][2]);
            acc[r][3] = fmaf(xv.y, w1.w, acc[r][3]);
            acc[r][0] = fmaf(xv.z, w2.x, acc[r][0]);
            acc[r][1] = fmaf(xv.z, w2.y, acc[r][1]);
            acc[r][2] = fmaf(xv.z, w2.z, acc[r][2]);
            acc[r][3] = fmaf(xv.z, w2.w, acc[r][3]);
            acc[r][0] = fmaf(xv.w, w3.x, acc[r][0]);
            acc[r][1] = fmaf(xv.w, w3.y, acc[r][1]);
            acc[r][2] = fmaf(xv.w, w3.z, acc[r][2]);
            acc[r][3] = fmaf(xv.w, w3.w, acc[r][3]);
        }
    }
    float4 bv = *reinterpret_cast<const float4*>(&bih[sgate*64 + tx*4]);
    #pragma unroll
    for (int r = 0; r < 4; r++) {
        size_t base = (row0 + ty*4 + r) * 192 + sgate*64 + tx*4;
        *reinterpret_cast<float4*>(&g_gi[base]) =
            make_float4(acc[r][0] + bv.x, acc[r][1] + bv.y,
                        acc[r][2] + bv.z, acc[r][3] + bv.w);
    }
}

// ---------------- fused GRU: per-batch; 16 nodes/block, 4 nodes/thread ---------------
#define HP 20
__global__ void k_gru(const float* __restrict__ Whh, const float* __restrict__ bhh_g,
                      const float* __restrict__ Wout, const float* __restrict__ bout,
                      float* __restrict__ out, int nodebase) {
    extern __shared__ float sm[];
    float* Wt  = sm;                      // [64][192]
    float* h0s = Wt + 64*192;             // [64][HP]
    float* h1s = h0s + 64*HP;             // [64][HP]
    float* bs  = h1s + 64*HP;             // [192]
    float* pp  = bs + 192;                // [16][2]
    int tid = threadIdx.x;
    for (int i = tid; i < 192*64; i += 256) {
        int o = i >> 6, k = i & 63;
        Wt[k*192 + o] = Whh[i];
    }
    for (int i = tid; i < 192; i += 256) bs[i] = bhh_g[i];
    __syncthreads();

    int j  = tid & 63;
    int ng = tid >> 6;                    // 0..3, owns 4 nodes
    int node0 = nodebase + blockIdx.x * 16;
    float b_r = bs[j], b_z = bs[j + 64], b_n = bs[j + 128];

    const float* gp[4];
    #pragma unroll
    for (int i = 0; i < 4; i++)
        gp[i] = g_gi + (size_t)(node0 + ng*4 + i) * (TT*192);

    float h[4];
    #pragma unroll
    for (int i = 0; i < 4; i++) {
        float gr = __ldg(gp[i] + j), gz = __ldg(gp[i] + 64 + j), gn = __ldg(gp[i] + 128 + j);
        float r = 1.f/(1.f + __expf(-(gr + b_r)));
        float z = 1.f/(1.f + __expf(-(gz + b_z)));
        float n = tanhf(gn + r*b_n);
        h[i] = (1.f - z)*n;
    }
    #pragma unroll
    for (int i = 0; i < 4; i++) h0s[j*HP + ng*4 + i] = h[i];
    __syncthreads();

    for (int t = 1; t < TT; t++) {
        float* hin  = ((t - 1) & 1) ? h1s : h0s;
        float* hout = (t & 1) ? h1s : h0s;
        float ar[4], az[4], an[4];
        #pragma unroll
        for (int i = 0; i < 4; i++) { ar[i] = 0.f; az[i] = 0.f; an[i] = 0.f; }
        #pragma unroll 4
        for (int k = 0; k < 64; k++) {
            float w0 = Wt[k*192 + j];
            float w1 = Wt[k*192 + 64 + j];
            float w2 = Wt[k*192 + 128 + j];
            float4 hv = *reinterpret_cast<float4*>(&hin[k*HP + ng*4]);
            float hvv[4] = {hv.x, hv.y, hv.z, hv.w};
            #pragma unroll
            for (int i = 0; i < 4; i++) {
                ar[i] = fmaf(hvv[i], w0, ar[i]);
                az[i] = fmaf(hvv[i], w1, az[i]);
                an[i] = fmaf(hvv[i], w2, an[i]);
            }
        }
        #pragma unroll
        for (int i = 0; i < 4; i++) {
            float gr = __ldg(gp[i] + t*192 + j);
            float gz = __ldg(gp[i] + t*192 + 64 + j);
            float gn = __ldg(gp[i] + t*192 + 128 + j);
            float r = 1.f/(1.f + __expf(-(gr + ar[i] + b_r)));
            float z = 1.f/(1.f + __expf(-(gz + az[i] + b_z)));
            float n = tanhf(gn + r*(an[i] + b_n));
            h[i] = (1.f - z)*n + z*h[i];
        }
        #pragma unroll
        for (int i = 0; i < 4; i++) hout[j*HP + ng*4 + i] = h[i];
        __syncthreads();
    }

    #pragma unroll
    for (int i = 0; i < 4; i++)
        out[8000 + (size_t)(node0 + ng*4 + i)*GHH + j] = h[i];
    float wj = __ldg(&Wout[j]);
    int half = (j >> 5);
    #pragma unroll
    for (int i = 0; i < 4; i++) {
        float p = h[i] * wj;
        #pragma unroll
        for (int o = 16; o; o >>= 1) p += __shfl_xor_sync(0xFFFFFFFFu, p, o);
        if ((j & 31) == 0) pp[(ng*4 + i)*2 + half] = p;
    }
    __syncthreads();
    if (tid < 16)
        out[node0 + tid] = pp[tid*2] + pp[tid*2 + 1] + __ldg(&bout[0]);
}

// ---------------- launch: 3-stream software pipeline over batches --------------------
extern "C" void kernel_launch(void* const* d_in, const int* in_sizes, int n_in,
                              void* d_out, int out_size) {
    const float* node_features = (const float*)d_in[0];
    const float* edge_features = (const float*)d_in[1];
    const float* W_node  = (const float*)d_in[2];
    const float* W_edge  = (const float*)d_in[3];
    const float* att     = (const float*)d_in[4];
    const float* ln_gamma= (const float*)d_in[5];
    const float* ln_beta = (const float*)d_in[6];
    const float* W_ih    = (const float*)d_in[7];
    const float* W_hh    = (const float*)d_in[8];
    const float* b_ih    = (const float*)d_in[9];
    const float* b_hh    = (const float*)d_in[10];
    const float* W_out   = (const float*)d_in[11];
    const float* b_out   = (const float*)d_in[12];
    const int*   edge_index = (const int*)d_in[13];   // int32 (JAX x64 off)
    float* out = (float*)d_out;

    static cudaStream_t sB = nullptr, sC = nullptr;
    static cudaEvent_t evStart, evNode, evGat[BB], evGi[BB], evGruLast;
    static int inited = 0;
    if (!inited) {
        cudaStreamCreateWithFlags(&sB, cudaStreamNonBlocking);
        cudaStreamCreateWithFlags(&sC, cudaStreamNonBlocking);
        cudaEventCreateWithFlags(&evStart, cudaEventDisableTiming);
        cudaEventCreateWithFlags(&evNode,  cudaEventDisableTiming);
        for (int b = 0; b < BB; b++) {
            cudaEventCreateWithFlags(&evGat[b], cudaEventDisableTiming);
            cudaEventCreateWithFlags(&evGi[b],  cudaEventDisableTiming);
        }
        cudaEventCreateWithFlags(&evGruLast, cudaEventDisableTiming);
        cudaFuncSetAttribute(k_gru, cudaFuncAttributeMaxDynamicSharedMemorySize,
                             (64*192 + 2*64*HP + 192 + 32) * 4);
        inited = 1;
    }
    int gru_smem = (64*192 + 2*64*HP + 192 + 32) * 4;

    // fork
    cudaEventRecord(evStart, 0);
    cudaStreamWaitEvent(sB, evStart, 0);
    cudaStreamWaitEvent(sC, evStart, 0);

    // main stream: CSR chain (sortB profiled at launch idx 3)
    k_count<<<(NEDGE + 255)/256, 256>>>(edge_index);                  // 0
    k_scan <<<1, 1024>>>();                                           // 1
    k_fillA<<<(NEDGE + 255)/256, 256>>>();                            // 2
    k_sortB<<<(NNODE*32 + 255)/256, 256>>>();                         // 3 <- profiled

    // side stream sB: prep + node (independent of CSR)
    k_prep<<<1, 128, 0, sB>>>(W_node, W_edge, att);
    k_node<<<(BT*NNODE + 255)/256, 256, 0, sB>>>(node_features);
    cudaEventRecord(evNode, sB);
    cudaStreamWaitEvent(0, evNode, 0);

    // pipeline over batches: gat(b) on s0 -> gi(b) on sB -> gru(b) on sC
    dim3 ggrid(NNODE/8, TT);
    dim3 gigrid((NNODE*TT)/64, 3);
    for (int b = 0; b < BB; b++) {
        k_gat<<<ggrid, 256>>>(node_features, edge_features, W_node, W_edge,
                              ln_gamma, ln_beta, b*TT);
        cudaEventRecord(evGat[b], 0);

        cudaStreamWaitEvent(sB, evGat[b], 0);
        k_gi<<<gigrid, 256, 0, sB>>>(W_ih, b_ih, b*NNODE*TT);
        cudaEventRecord(evGi[b], sB);

        cudaStreamWaitEvent(sC, evGi[b], 0);
        k_gru<<<NNODE/16, 256, gru_smem, sC>>>(W_hh, b_hh, W_out, b_out, out, b*NNODE);
    }
    cudaEventRecord(evGruLast, sC);

    // attn on s0 after all gat (in-order), concurrent with tail gi/gru
    k_attn<<<(TT*NEDGE + 255)/256, 256>>>(out + 8000 + (size_t)BB*NNODE*GHH);

    // join
    cudaStreamWaitEvent(0, evGruLast, 0);
}

// round 16
// speedup vs baseline: 1.0651x; 1.0651x over previous
#include <cuda_runtime.h>
#include <cstdint>
#include <cstdio>

#define BB 4
#define TT 12
#define NNODE 2000
#define NEDGE 32000
#define NDIM 16
#define EDIM 8
#define NH 4
#define DD 16
#define GG 64
#define GHH 64
#define BT 48   // BB*TT

// ---------------- scratch (device globals) ----------------
static __device__ float    g_sd  [(size_t)BT*NNODE*NH];
static __device__ float    g_ss  [(size_t)BT*NNODE*NH];
static __device__ float    g_score[(size_t)BT*NEDGE*NH];    // ALPHA
static __device__ float    g_gin [(size_t)BB*NNODE*TT*GG];  // LN out, row=(b*N+n)*T+t
static __device__ float    g_gi  [(size_t)BB*NNODE*TT*3*GHH];
static __device__ float    g_Md[NDIM*NH], g_Ms[NDIM*NH], g_Me[EDIM*NH];
static __device__ int      g_src[NEDGE], g_dst[NEDGE];
static __device__ int      g_deg[NNODE];                    // zero at entry (re-zeroed by scan)
static __device__ int      g_cur[NNODE];
static __device__ int      g_off[NNODE+1], g_csr[NEDGE];

// ---------------- csr 1: copy edge list + count degrees ----------------
__global__ void k_count(const int* __restrict__ ei) {
    int e = blockIdx.x * blockDim.x + threadIdx.x;
    if (e < NEDGE) {
        int s = ei[e], d = ei[NEDGE + e];
        g_src[e] = s; g_dst[e] = d;
        atomicAdd(&g_deg[d], 1);
    }
}

// ---------------- csr 2: scan + re-zero g_deg ----------------
__global__ void k_scan() {
    __shared__ int sa[2048], sb[2048];
    int tid = threadIdx.x;                 // 1024
    for (int i = tid; i < 2048; i += 1024) {
        sa[i] = (i < NNODE) ? g_deg[i] : 0;
        if (i < NNODE) g_deg[i] = 0;       // restore invariant for graph replay
    }
    __syncthreads();
    int* cur = sa; int* nxt = sb;
    for (int d = 1; d < 2048; d <<= 1) {
        for (int i = tid; i < 2048; i += 1024)
            nxt[i] = (i >= d) ? cur[i] + cur[i - d] : cur[i];
        __syncthreads();
        int* t = cur; cur = nxt; nxt = t;
    }
    for (int i = tid; i < NNODE; i += 1024) {
        int off = (i == 0) ? 0 : cur[i - 1];
        g_off[i] = off;
        g_cur[i] = off;
    }
    if (tid == 0) g_off[NNODE] = cur[NNODE - 1];
}

// ---------------- csr 3: atomic fill ----------------
__global__ void k_fillA() {
    int e = blockIdx.x * blockDim.x + threadIdx.x;
    if (e < NEDGE) {
        int pos = atomicAdd(&g_cur[g_dst[e]], 1);
        g_csr[pos] = e;
    }
}

// ---------------- csr 4: warp-per-node bitonic sort ----------------
__global__ void k_sortB() {
    int gw   = (blockIdx.x * blockDim.x + threadIdx.x) >> 5;
    int lane = threadIdx.x & 31;
    if (gw >= NNODE) return;
    int off = g_off[gw];
    int deg = g_off[gw + 1] - off;
    if (deg <= 1) return;
    if (deg <= 32) {
        int v = (lane < deg) ? g_csr[off + lane] : 0x7FFFFFFF;
        #pragma unroll
        for (int k = 2; k <= 32; k <<= 1) {
            #pragma unroll
            for (int j = k >> 1; j > 0; j >>= 1) {
                int o = __shfl_xor_sync(0xFFFFFFFFu, v, j);
                bool lower = (lane & j) == 0;
                bool asc   = (lane & k) == 0;
                v = (lower == asc) ? min(v, o) : max(v, o);
            }
        }
        if (lane < deg) g_csr[off + lane] = v;
    } else if (lane == 0) {
        for (int i = 1; i < deg; i++) {
            int v = g_csr[off + i], k = i - 1;
            while (k >= 0 && g_csr[off + k] > v) { g_csr[off + k + 1] = g_csr[off + k]; k--; }
            g_csr[off + k + 1] = v;
        }
    }
}

// ---------------- prep: fold att vectors into tiny matrices (side stream) ----------
__global__ void k_prep(const float* __restrict__ Wn, const float* __restrict__ We,
                       const float* __restrict__ att) {
    int tid = threadIdx.x;
    if (tid < NDIM*NH) {
        int c = tid >> 2, h = tid & 3;
        float s0 = 0.f, s1 = 0.f;
        #pragma unroll
        for (int d = 0; d < DD; d++) {
            float w = Wn[c*GG + h*DD + d];
            s0 += w * att[h*(3*DD) + d];
            s1 += w * att[h*(3*DD) + DD + d];
        }
        g_Md[c*NH + h] = s0;
        g_Ms[c*NH + h] = s1;
    } else if (tid < NDIM*NH + EDIM*NH) {
        int k = tid - NDIM*NH;
        int c = k >> 2, h = k & 3;
        float s = 0.f;
        #pragma unroll
        for (int d = 0; d < DD; d++)
            s += We[c*GG + h*DD + d] * att[h*(3*DD) + 2*DD + d];
        g_Me[c*NH + h] = s;
    }
}

// ---------------- node score terms: sd/ss = x @ Md / Ms ----------------
__global__ void k_node(const float* __restrict__ xf) {
    int gn = blockIdx.x * blockDim.x + threadIdx.x;   // [0, BT*NNODE)
    if (gn >= BT*NNODE) return;
    const float* xp = xf + (size_t)gn * NDIM;
    float x[NDIM];
    #pragma unroll
    for (int c = 0; c < NDIM; c += 4) {
        float4 v = *reinterpret_cast<const float4*>(xp + c);
        x[c] = v.x; x[c+1] = v.y; x[c+2] = v.z; x[c+3] = v.w;
    }
    float sd[NH] = {0.f,0.f,0.f,0.f}, ss[NH] = {0.f,0.f,0.f,0.f};
    #pragma unroll
    for (int c = 0; c < NDIM; c++) {
        float4 md = *reinterpret_cast<const float4*>(&g_Md[c*NH]);
        float4 ms = *reinterpret_cast<const float4*>(&g_Ms[c*NH]);
        sd[0] = fmaf(x[c], md.x, sd[0]); sd[1] = fmaf(x[c], md.y, sd[1]);
        sd[2] = fmaf(x[c], md.z, sd[2]); sd[3] = fmaf(x[c], md.w, sd[3]);
        ss[0] = fmaf(x[c], ms.x, ss[0]); ss[1] = fmaf(x[c], ms.y, ss[1]);
        ss[2] = fmaf(x[c], ms.z, ss[2]); ss[3] = fmaf(x[c], ms.w, ss[3]);
    }
    *reinterpret_cast<float4*>(&g_sd[(size_t)gn*NH]) = make_float4(sd[0], sd[1], sd[2], sd[3]);
    *reinterpret_cast<float4*>(&g_ss[(size_t)gn*NH]) = make_float4(ss[0], ss[1], ss[2], ss[3]);
}

// ---------------- k_gat: fused softmax + x-space aggregation + proj + ELU + LN -------
__global__ void __launch_bounds__(256) k_gat(const float* __restrict__ xf,
                                             const float* __restrict__ efeat,
                                             const float* __restrict__ Wn,
                                             const float* __restrict__ We,
                                             const float* __restrict__ gamma,
                                             const float* __restrict__ beta) {
    __shared__ float s_al [8][32*4];
    __shared__ float s_ef [8][32*8];
    __shared__ int   s_src[8][32];
    __shared__ float s_axs[8][64];
    __shared__ float s_aef[8][32];

    int g    = blockIdx.y;
    int warp = threadIdx.x >> 5;
    int lane = threadIdx.x & 31;
    int node = blockIdx.x * 8 + warp;
    unsigned gE = (unsigned)g * NEDGE;
    unsigned gN = (unsigned)g * NNODE;
    const float* xg = xf + (size_t)gN * NDIM;
    const float* eg = efeat + (size_t)gE * EDIM;

    int off = g_off[node];
    int deg = g_off[node + 1] - off;
    float4 sd4 = *reinterpret_cast<const float4*>(&g_sd[(size_t)(gN + node)*NH]);

    int hA  = lane >> 4;
    int cA  = lane & 15;
    int hM  = lane >> 3;
    int cM  = lane & 7;
    float axs0 = 0.f, axs1 = 0.f, aef = 0.f;

    if (deg <= 32) {
        bool v = lane < deg;
        int e = 0, src = 0;
        float4 ea = make_float4(0.f,0.f,0.f,0.f), eb = ea, ss4 = ea;
        if (v) {
            e = g_csr[off + lane];
            src = g_src[e];
            const float* ef = eg + e*EDIM;
            ea = *reinterpret_cast<const float4*>(ef);
            eb = *reinterpret_cast<const float4*>(ef + 4);
            ss4 = *reinterpret_cast<const float4*>(&g_ss[(size_t)(gN + src)*NH]);
        }
        float efv[8] = {ea.x, ea.y, ea.z, ea.w, eb.x, eb.y, eb.z, eb.w};
        float s0 = sd4.x + ss4.x, s1 = sd4.y + ss4.y;
        float s2 = sd4.z + ss4.z, s3 = sd4.w + ss4.w;
        #pragma unroll
        for (int c = 0; c < EDIM; c++) {
            float4 me = *reinterpret_cast<const float4*>(&g_Me[c*NH]);
            s0 = fmaf(efv[c], me.x, s0);
            s1 = fmaf(efv[c], me.y, s1);
            s2 = fmaf(efv[c], me.z, s2);
            s3 = fmaf(efv[c], me.w, s3);
        }
        s0 = (s0 > 0.f) ? s0 : 0.2f*s0;  s1 = (s1 > 0.f) ? s1 : 0.2f*s1;
        s2 = (s2 > 0.f) ? s2 : 0.2f*s2;  s3 = (s3 > 0.f) ? s3 : 0.2f*s3;
        if (!v) { s0 = s1 = s2 = s3 = -1e30f; }
        float m0 = s0, m1 = s1, m2 = s2, m3 = s3;
        #pragma unroll
        for (int o = 16; o; o >>= 1) {
            m0 = fmaxf(m0, __shfl_xor_sync(0xFFFFFFFFu, m0, o));
            m1 = fmaxf(m1, __shfl_xor_sync(0xFFFFFFFFu, m1, o));
            m2 = fmaxf(m2, __shfl_xor_sync(0xFFFFFFFFu, m2, o));
            m3 = fmaxf(m3, __shfl_xor_sync(0xFFFFFFFFu, m3, o));
        }
        float e0 = v ? __expf(s0 - m0) : 0.f;
        float e1 = v ? __expf(s1 - m1) : 0.f;
        float e2 = v ? __expf(s2 - m2) : 0.f;
        float e3 = v ? __expf(s3 - m3) : 0.f;
        float t0 = e0, t1 = e1, t2 = e2, t3 = e3;
        #pragma unroll
        for (int o = 16; o; o >>= 1) {
            t0 += __shfl_xor_sync(0xFFFFFFFFu, t0, o);
            t1 += __shfl_xor_sync(0xFFFFFFFFu, t1, o);
            t2 += __shfl_xor_sync(0xFFFFFFFFu, t2, o);
            t3 += __shfl_xor_sync(0xFFFFFFFFu, t3, o);
        }
        if (v) {
            float4 al = make_float4(e0/(t0 + 1e-16f), e1/(t1 + 1e-16f),
                                    e2/(t2 + 1e-16f), e3/(t3 + 1e-16f));
            *reinterpret_cast<float4*>(&g_score[(size_t)(gE + e)*NH]) = al;
            s_src[warp][lane] = src;
            *reinterpret_cast<float4*>(&s_al[warp][lane*4]) = al;
            *reinterpret_cast<float4*>(&s_ef[warp][lane*8])     = ea;
            *reinterpret_cast<float4*>(&s_ef[warp][lane*8 + 4]) = eb;
        }
        __syncwarp();
        for (int i = 0; i < deg; i++) {
            int s = s_src[warp][i];
            float a_lo = s_al[warp][i*4 + hA];
            float a_hi = s_al[warp][i*4 + 2 + hA];
            float xv = __ldg(&xg[s*NDIM + cA]);
            axs0 = fmaf(a_lo, xv, axs0);
            axs1 = fmaf(a_hi, xv, axs1);
            aef  = fmaf(s_al[warp][i*4 + hM], s_ef[warp][i*8 + cM], aef);
        }
    } else {
        float m0 = -1e30f, m1 = -1e30f, m2 = -1e30f, m3 = -1e30f;
        for (int i = lane; i < deg; i += 32) {
            int e = g_csr[off + i];
            const float* ef = eg + e*EDIM;
            float4 ea = *reinterpret_cast<const float4*>(ef);
            float4 eb = *reinterpret_cast<const float4*>(ef + 4);
            float efv[8] = {ea.x, ea.y, ea.z, ea.w, eb.x, eb.y, eb.z, eb.w};
            float4 ss4 = *reinterpret_cast<const float4*>(&g_ss[(size_t)(gN + g_src[e])*NH]);
            float s0 = sd4.x + ss4.x, s1 = sd4.y + ss4.y;
            float s2 = sd4.z + ss4.z, s3 = sd4.w + ss4.w;
            #pragma unroll
            for (int c = 0; c < EDIM; c++) {
                float4 me = *reinterpret_cast<const float4*>(&g_Me[c*NH]);
                s0 = fmaf(efv[c], me.x, s0);
                s1 = fmaf(efv[c], me.y, s1);
                s2 = fmaf(efv[c], me.z, s2);
                s3 = fmaf(efv[c], me.w, s3);
            }
            s0 = (s0 > 0.f) ? s0 : 0.2f*s0;  s1 = (s1 > 0.f) ? s1 : 0.2f*s1;
            s2 = (s2 > 0.f) ? s2 : 0.2f*s2;  s3 = (s3 > 0.f) ? s3 : 0.2f*s3;
            *reinterpret_cast<float4*>(&g_score[(size_t)(gE + e)*NH]) = make_float4(s0, s1, s2, s3);
            m0 = fmaxf(m0, s0); m1 = fmaxf(m1, s1);
            m2 = fmaxf(m2, s2); m3 = fmaxf(m3, s3);
        }
        #pragma unroll
        for (int o = 16; o; o >>= 1) {
            m0 = fmaxf(m0, __shfl_xor_sync(0xFFFFFFFFu, m0, o));
            m1 = fmaxf(m1, __shfl_xor_sync(0xFFFFFFFFu, m1, o));
            m2 = fmaxf(m2, __shfl_xor_sync(0xFFFFFFFFu, m2, o));
            m3 = fmaxf(m3, __shfl_xor_sync(0xFFFFFFFFu, m3, o));
        }
        float t0 = 0.f, t1 = 0.f, t2 = 0.f, t3 = 0.f;
        for (int i = lane; i < deg; i += 32) {
            int e = g_csr[off + i];
            float4 sc = *reinterpret_cast<const float4*>(&g_score[(size_t)(gE + e)*NH]);
            float e0 = __expf(sc.x - m0), e1 = __expf(sc.y - m1);
            float e2 = __expf(sc.z - m2), e3 = __expf(sc.w - m3);
            *reinterpret_cast<float4*>(&g_score[(size_t)(gE + e)*NH]) = make_float4(e0, e1, e2, e3);
            t0 += e0; t1 += e1; t2 += e2; t3 += e3;
        }
        #pragma unroll
        for (int o = 16; o; o >>= 1) {
            t0 += __shfl_xor_sync(0xFFFFFFFFu, t0, o);
            t1 += __shfl_xor_sync(0xFFFFFFFFu, t1, o);
            t2 += __shfl_xor_sync(0xFFFFFFFFu, t2, o);
            t3 += __shfl_xor_sync(0xFFFFFFFFu, t3, o);
        }
        float r0 = 1.f/(t0 + 1e-16f), r1 = 1.f/(t1 + 1e-16f);
        float r2 = 1.f/(t2 + 1e-16f), r3 = 1.f/(t3 + 1e-16f);
        for (int i = lane; i < deg; i += 32) {
            int e = g_csr[off + i];
            float4 es = *reinterpret_cast<const float4*>(&g_score[(size_t)(gE + e)*NH]);
            *reinterpret_cast<float4*>(&g_score[(size_t)(gE + e)*NH]) =
                make_float4(es.x*r0, es.y*r1, es.z*r2, es.w*r3);
        }
        __threadfence();
        __syncwarp();
        for (int i = 0; i < deg; i++) {
            int e = g_csr[off + i];
            int s = __ldg(&g_src[e]);
            const float* ap = &g_score[(size_t)(gE + e)*NH];
            float a_lo = __ldg(ap + hA);
            float a_hi = __ldg(ap + 2 + hA);
            float a_me = __ldg(ap + hM);
            float xv   = __ldg(&xg[s*NDIM + cA]);
            float ev   = __ldg(&eg[e*EDIM + cM]);
            axs0 = fmaf(a_lo, xv, axs0);
            axs1 = fmaf(a_hi, xv, axs1);
            aef  = fmaf(a_me, ev, aef);
        }
    }

    s_axs[warp][hA*16 + cA]       = axs0;
    s_axs[warp][(2 + hA)*16 + cA] = axs1;
    s_aef[warp][lane] = aef;
    __syncwarp();

    float o01[2];
    #pragma unroll
    for (int half = 0; half < 2; half++) {
        int j = lane + half*32;
        int h = j >> 4;
        float acc = 0.f;
        #pragma unroll
        for (int c = 0; c < NDIM; c++)
            acc = fmaf(s_axs[warp][h*16 + c], __ldg(&Wn[c*GG + j]), acc);
        #pragma unroll
        for (int c = 0; c < EDIM; c++)
            acc = fmaf(s_aef[warp][h*8 + c], __ldg(&We[c*GG + j]), acc);
        o01[half] = (acc > 0.f) ? acc : (__expf(acc) - 1.f);
    }
    float s = o01[0] + o01[1];
    float q = o01[0]*o01[0] + o01[1]*o01[1];
    #pragma unroll
    for (int o = 16; o; o >>= 1) {
        s += __shfl_xor_sync(0xFFFFFFFFu, s, o);
        q += __shfl_xor_sync(0xFFFFFFFFu, q, o);
    }
    float mu = s * (1.f/GG);
    float inv = rsqrtf(q * (1.f/GG) - mu*mu + 1e-5f);
    int b = g / TT, t = g - b*TT;
    size_t gb = (((size_t)b*NNODE + node)*TT + t)*GG;
    g_gin[gb + lane]      = (o01[0] - mu)*inv*__ldg(&gamma[lane])      + __ldg(&beta[lane]);
    g_gin[gb + lane + 32] = (o01[1] - mu)*inv*__ldg(&gamma[lane + 32]) + __ldg(&beta[lane + 32]);
}

// ---------------- attention output ----------------
__global__ void k_attn(float* __restrict__ out3) {
    int te = blockIdx.x * blockDim.x + threadIdx.x;
    if (te >= TT*NEDGE) return;
    int e = te % NEDGE;
    int t = te / NEDGE;
    float4 s = make_float4(0.f, 0.f, 0.f, 0.f);
    #pragma unroll
    for (int b = 0; b < BB; b++) {
        float4 v = *reinterpret_cast<const float4*>(
            &g_score[(((size_t)(b*TT + t))*NEDGE + e)*NH]);
        s.x += v.x; s.y += v.y; s.z += v.z; s.w += v.w;
    }
    s.x *= 0.25f; s.y *= 0.25f; s.z *= 0.25f; s.w *= 0.25f;
    *reinterpret_cast<float4*>(&out3[(size_t)te*NH]) = s;
}

// ---------------- gi GEMM: gate-split 64x64, 4r x 4c/thread; half-range param -------
__global__ void __launch_bounds__(256) k_gi(const float* __restrict__ Wih,
                                            const float* __restrict__ bih,
                                            int rowbase) {
    __shared__ float Ws[64*64];      // Ws[k*64+o]
    __shared__ float X [64*68];      // X[r*68+k]
    int tid = threadIdx.x;
    int sgate = blockIdx.y;          // 0..2
    for (int i = tid; i < 64*64; i += 256) {
        int o = i >> 6, k = i & 63;
        Ws[k*64 + o] = Wih[(size_t)(sgate*64 + o)*64 + k];
    }
    size_t row0 = (size_t)rowbase + (size_t)blockIdx.x * 64;
    for (int i = tid; i < 64*64; i += 256) {
        int r = i >> 6, k = i & 63;
        X[r*68 + k] = g_gin[row0*GG + i];
    }
    __syncthreads();
    int tx = tid & 15;               // cols tx*4..+4
    int ty = tid >> 4;               // rows ty*4..+4
    float acc[4][4];
    #pragma unroll
    for (int r = 0; r < 4; r++)
        #pragma unroll
        for (int c = 0; c < 4; c++) acc[r][c] = 0.f;
    #pragma unroll 4
    for (int k = 0; k < 64; k += 4) {
        float4 w0 = *reinterpret_cast<float4*>(&Ws[(k+0)*64 + tx*4]);
        float4 w1 = *reinterpret_cast<float4*>(&Ws[(k+1)*64 + tx*4]);
        float4 w2 = *reinterpret_cast<float4*>(&Ws[(k+2)*64 + tx*4]);
        float4 w3 = *reinterpret_cast<float4*>(&Ws[(k+3)*64 + tx*4]);
        #pragma unroll
        for (int r = 0; r < 4; r++) {
            float4 xv = *reinterpret_cast<float4*>(&X[(ty*4 + r)*68 + k]);
            acc[r][0] = fmaf(xv.x, w0.x, acc[r][0]);
            acc[r][1] = fmaf(xv.x, w0.y, acc[r][1]);
            acc[r][2] = fmaf(xv.x, w0.z, acc[r][2]);
            acc[r][3] = fmaf(xv.x, w0.w, acc[r][3]);
            acc[r][0] = fmaf(xv.y, w1.x, acc[r][0]);
            acc[r][1] = fmaf(xv.y, w1.y, acc[r][1]);
            acc[r][2] = fmaf(xv.y, w1.z, acc[r][2]);
            acc[r][3] = fmaf(xv.y, w1.w, acc[r][3]);
            acc[r][0] = fmaf(xv.z, w2.x, acc[r][0]);
            acc[r][1] = fmaf(xv.z, w2.y, acc[r][1]);
            acc[r][2] = fmaf(xv.z, w2.z, acc[r][2]);
            acc[r][3] = fmaf(xv.z, w2.w, acc[r][3]);
            acc[r][0] = fmaf(xv.w, w3.x, acc[r][0]);
            acc[r][1] = fmaf(xv.w, w3.y, acc[r][1]);
            acc[r][2] = fmaf(xv.w, w3.z, acc[r][2]);
            acc[r][3] = fmaf(xv.w, w3.w, acc[r][3]);
        }
    }
    float4 bv = *reinterpret_cast<const float4*>(&bih[sgate*64 + tx*4]);
    #pragma unroll
    for (int r = 0; r < 4; r++) {
        size_t base = (row0 + ty*4 + r) * 192 + sgate*64 + tx*4;
        *reinterpret_cast<float4*>(&g_gi[base]) =
            make_float4(acc[r][0] + bv.x, acc[r][1] + bv.y,
                        acc[r][2] + bv.z, acc[r][3] + bv.w);
    }
}

// ---------------- fused GRU: 16 nodes/block, 4 nodes/thread; half-range param --------
#define HP 20
__global__ void k_gru(const float* __restrict__ Whh, const float* __restrict__ bhh_g,
                      const float* __restrict__ Wout, const float* __restrict__ bout,
                      float* __restrict__ out, int nodebase) {
    extern __shared__ float sm[];
    float* Wt  = sm;                      // [64][192]
    float* h0s = Wt + 64*192;             // [64][HP]
    float* h1s = h0s + 64*HP;             // [64][HP]
    float* bs  = h1s + 64*HP;             // [192]
    float* pp  = bs + 192;                // [16][2]
    int tid = threadIdx.x;
    for (int i = tid; i < 192*64; i += 256) {
        int o = i >> 6, k = i & 63;
        Wt[k*192 + o] = Whh[i];
    }
    for (int i = tid; i < 192; i += 256) bs[i] = bhh_g[i];
    __syncthreads();

    int j  = tid & 63;
    int ng = tid >> 6;                    // 0..3, owns 4 nodes
    int node0 = nodebase + blockIdx.x * 16;
    float b_r = bs[j], b_z = bs[j + 64], b_n = bs[j + 128];

    const float* gp[4];
    #pragma unroll
    for (int i = 0; i < 4; i++)
        gp[i] = g_gi + (size_t)(node0 + ng*4 + i) * (TT*192);

    float h[4];
    #pragma unroll
    for (int i = 0; i < 4; i++) {
        float gr = __ldg(gp[i] + j), gz = __ldg(gp[i] + 64 + j), gn = __ldg(gp[i] + 128 + j);
        float r = 1.f/(1.f + __expf(-(gr + b_r)));
        float z = 1.f/(1.f + __expf(-(gz + b_z)));
        float n = tanhf(gn + r*b_n);
        h[i] = (1.f - z)*n;
    }
    #pragma unroll
    for (int i = 0; i < 4; i++) h0s[j*HP + ng*4 + i] = h[i];
    __syncthreads();

    for (int t = 1; t < TT; t++) {
        float* hin  = ((t - 1) & 1) ? h1s : h0s;
        float* hout = (t & 1) ? h1s : h0s;
        float ar[4], az[4], an[4];
        #pragma unroll
        for (int i = 0; i < 4; i++) { ar[i] = 0.f; az[i] = 0.f; an[i] = 0.f; }
        #pragma unroll 4
        for (int k = 0; k < 64; k++) {
            float w0 = Wt[k*192 + j];
            float w1 = Wt[k*192 + 64 + j];
            float w2 = Wt[k*192 + 128 + j];
            float4 hv = *reinterpret_cast<float4*>(&hin[k*HP + ng*4]);
            float hvv[4] = {hv.x, hv.y, hv.z, hv.w};
            #pragma unroll
            for (int i = 0; i < 4; i++) {
                ar[i] = fmaf(hvv[i], w0, ar[i]);
                az[i] = fmaf(hvv[i], w1, az[i]);
                an[i] = fmaf(hvv[i], w2, an[i]);
            }
        }
        #pragma unroll
        for (int i = 0; i < 4; i++) {
            float gr = __ldg(gp[i] + t*192 + j);
            float gz = __ldg(gp[i] + t*192 + 64 + j);
            float gn = __ldg(gp[i] + t*192 + 128 + j);
            float r = 1.f/(1.f + __expf(-(gr + ar[i] + b_r)));
            float z = 1.f/(1.f + __expf(-(gz + az[i] + b_z)));
            float n = tanhf(gn + r*(an[i] + b_n));
            h[i] = (1.f - z)*n + z*h[i];
        }
        #pragma unroll
        for (int i = 0; i < 4; i++) hout[j*HP + ng*4 + i] = h[i];
        __syncthreads();
    }

    #pragma unroll
    for (int i = 0; i < 4; i++)
        out[8000 + (size_t)(node0 + ng*4 + i)*GHH + j] = h[i];
    float wj = __ldg(&Wout[j]);
    int half = (j >> 5);
    #pragma unroll
    for (int i = 0; i < 4; i++) {
        float p = h[i] * wj;
        #pragma unroll
        for (int o = 16; o; o >>= 1) p += __shfl_xor_sync(0xFFFFFFFFu, p, o);
        if ((j & 31) == 0) pp[(ng*4 + i)*2 + half] = p;
    }
    __syncthreads();
    if (tid < 16)
        out[node0 + tid] = pp[tid*2] + pp[tid*2 + 1] + __ldg(&bout[0]);
}

// ---------------- launch: R14 fork-join + 2-deep gi/gru half pipeline ----------------
extern "C" void kernel_launch(void* const* d_in, const int* in_sizes, int n_in,
                              void* d_out, int out_size) {
    const float* node_features = (const float*)d_in[0];
    const float* edge_features = (const float*)d_in[1];
    const float* W_node  = (const float*)d_in[2];
    const float* W_edge  = (const float*)d_in[3];
    const float* att     = (const float*)d_in[4];
    const float* ln_gamma= (const float*)d_in[5];
    const float* ln_beta = (const float*)d_in[6];
    const float* W_ih    = (const float*)d_in[7];
    const float* W_hh    = (const float*)d_in[8];
    const float* b_ih    = (const float*)d_in[9];
    const float* b_hh    = (const float*)d_in[10];
    const float* W_out   = (const float*)d_in[11];
    const float* b_out   = (const float*)d_in[12];
    const int*   edge_index = (const int*)d_in[13];   // int32 (JAX x64 off)
    float* out = (float*)d_out;

    static cudaStream_t sB = nullptr, sC = nullptr;
    static cudaEvent_t evStart, evNode, evGat, evGi0, evGi1, evGruLast, evAttn;
    static int inited = 0;
    if (!inited) {
        cudaStreamCreateWithFlags(&sB, cudaStreamNonBlocking);
        cudaStreamCreateWithFlags(&sC, cudaStreamNonBlocking);
        cudaEventCreateWithFlags(&evStart, cudaEventDisableTiming);
        cudaEventCreateWithFlags(&evNode,  cudaEventDisableTiming);
        cudaEventCreateWithFlags(&evGat,   cudaEventDisableTiming);
        cudaEventCreateWithFlags(&evGi0,   cudaEventDisableTiming);
        cudaEventCreateWithFlags(&evGi1,   cudaEventDisableTiming);
        cudaEventCreateWithFlags(&evGruLast, cudaEventDisableTiming);
        cudaEventCreateWithFlags(&evAttn,  cudaEventDisableTiming);
        cudaFuncSetAttribute(k_gru, cudaFuncAttributeMaxDynamicSharedMemorySize,
                             (64*192 + 2*64*HP + 192 + 32) * 4);
        inited = 1;
    }
    int gru_smem = (64*192 + 2*64*HP + 192 + 32) * 4;

    // fork
    cudaEventRecord(evStart, 0);
    cudaStreamWaitEvent(sB, evStart, 0);
    cudaStreamWaitEvent(sC, evStart, 0);

    // main stream: CSR chain (sortB profiled at launch idx 3)
    k_count<<<(NEDGE + 255)/256, 256>>>(edge_index);                  // 0
    k_scan <<<1, 1024>>>();                                           // 1
    k_fillA<<<(NEDGE + 255)/256, 256>>>();                            // 2
    k_sortB<<<(NNODE*32 + 255)/256, 256>>>();                         // 3 <- profiled

    // side stream sB: prep + node (independent of CSR)
    k_prep<<<1, 128, 0, sB>>>(W_node, W_edge, att);
    k_node<<<(BT*NNODE + 255)/256, 256, 0, sB>>>(node_features);
    cudaEventRecord(evNode, sB);
    cudaStreamWaitEvent(0, evNode, 0);

    // main: gat (whole, 12000 blocks)
    dim3 ggrid(NNODE/8, BT);
    k_gat<<<ggrid, 256>>>(node_features, edge_features, W_node, W_edge,
                          ln_gamma, ln_beta);
    cudaEventRecord(evGat, 0);

    // half pipeline: gi_h0 -> [gi_h1 || gru_h0] -> gru_h1
    const int HROWS = BB*NNODE*TT/2;   // 48000 rows per half
    const int HNODE = BB*NNODE/2;      // 4000 nodes per half
    dim3 gigrid(HROWS/64, 3);          // 750 x 3

    k_gi<<<gigrid, 256>>>(W_ih, b_ih, 0);                             // gi_h0 (s0)
    cudaEventRecord(evGi0, 0);

    k_gi<<<gigrid, 256>>>(W_ih, b_ih, HROWS);                         // gi_h1 (s0)
    cudaEventRecord(evGi1, 0);

    cudaStreamWaitEvent(sC, evGi0, 0);
    k_gru<<<HNODE/16, 256, gru_smem, sC>>>(W_hh, b_hh, W_out, b_out, out, 0);      // gru_h0 || gi_h1
    cudaStreamWaitEvent(sC, evGi1, 0);
    k_gru<<<HNODE/16, 256, gru_smem, sC>>>(W_hh, b_hh, W_out, b_out, out, HNODE);  // gru_h1
    cudaEventRecord(evGruLast, sC);

    // attn on sB after gat, concurrent with gi/gru
    cudaStreamWaitEvent(sB, evGat, 0);
    k_attn<<<(TT*NEDGE + 255)/256, 256, 0, sB>>>(out + 8000 + (size_t)BB*NNODE*GHH);
    cudaEventRecord(evAttn, sB);

    // join
    cudaStreamWaitEvent(0, evGruLast, 0);
    cudaStreamWaitEvent(0, evAttn, 0);
}

// round 17
// speedup vs baseline: 1.1584x; 1.0876x over previous
#include <cuda_runtime.h>
#include <cstdint>
#include <cstdio>

#define BB 4
#define TT 12
#define NNODE 2000
#define NEDGE 32000
#define NDIM 16
#define EDIM 8
#define NH 4
#define DD 16
#define GG 64
#define GHH 64
#define BT 48   // BB*TT

// ---------------- scratch (device globals) ----------------
static __device__ float    g_sd  [(size_t)BT*NNODE*NH];
static __device__ float    g_ss  [(size_t)BT*NNODE*NH];
static __device__ float    g_score[(size_t)BT*NEDGE*NH];    // ALPHA
static __device__ float    g_gin [(size_t)BB*NNODE*TT*GG];  // LN out, row=(b*N+n)*T+t
static __device__ float    g_gi  [(size_t)BB*NNODE*TT*3*GHH];
static __device__ float    g_Md[NDIM*NH], g_Ms[NDIM*NH], g_Me[EDIM*NH];
static __device__ int      g_src[NEDGE], g_dst[NEDGE];
static __device__ int      g_deg[NNODE];                    // zero at entry (re-zeroed by scan)
static __device__ int      g_cur[NNODE];
static __device__ int      g_off[NNODE+1], g_csr[NEDGE];

// ---------------- csr 1: copy edge list + count degrees ----------------
__global__ void k_count(const int* __restrict__ ei) {
    int e = blockIdx.x * blockDim.x + threadIdx.x;
    if (e < NEDGE) {
        int s = ei[e], d = ei[NEDGE + e];
        g_src[e] = s; g_dst[e] = d;
        atomicAdd(&g_deg[d], 1);
    }
}

// ---------------- csr 2: scan + re-zero g_deg ----------------
__global__ void k_scan() {
    __shared__ int sa[2048], sb[2048];
    int tid = threadIdx.x;                 // 1024
    for (int i = tid; i < 2048; i += 1024) {
        sa[i] = (i < NNODE) ? g_deg[i] : 0;
        if (i < NNODE) g_deg[i] = 0;       // restore invariant for graph replay
    }
    __syncthreads();
    int* cur = sa; int* nxt = sb;
    for (int d = 1; d < 2048; d <<= 1) {
        for (int i = tid; i < 2048; i += 1024)
            nxt[i] = (i >= d) ? cur[i] + cur[i - d] : cur[i];
        __syncthreads();
        int* t = cur; cur = nxt; nxt = t;
    }
    for (int i = tid; i < NNODE; i += 1024) {
        int off = (i == 0) ? 0 : cur[i - 1];
        g_off[i] = off;
        g_cur[i] = off;
    }
    if (tid == 0) g_off[NNODE] = cur[NNODE - 1];
}

// ---------------- csr 3: atomic fill ----------------
__global__ void k_fillA() {
    int e = blockIdx.x * blockDim.x + threadIdx.x;
    if (e < NEDGE) {
        int pos = atomicAdd(&g_cur[g_dst[e]], 1);
        g_csr[pos] = e;
    }
}

// ---------------- csr 4: warp-per-node bitonic sort ----------------
__global__ void k_sortB() {
    int gw   = (blockIdx.x * blockDim.x + threadIdx.x) >> 5;
    int lane = threadIdx.x & 31;
    if (gw >= NNODE) return;
    int off = g_off[gw];
    int deg = g_off[gw + 1] - off;
    if (deg <= 1) return;
    if (deg <= 32) {
        int v = (lane < deg) ? g_csr[off + lane] : 0x7FFFFFFF;
        #pragma unroll
        for (int k = 2; k <= 32; k <<= 1) {
            #pragma unroll
            for (int j = k >> 1; j > 0; j >>= 1) {
                int o = __shfl_xor_sync(0xFFFFFFFFu, v, j);
                bool lower = (lane & j) == 0;
                bool asc   = (lane & k) == 0;
                v = (lower == asc) ? min(v, o) : max(v, o);
            }
        }
        if (lane < deg) g_csr[off + lane] = v;
    } else if (lane == 0) {
        for (int i = 1; i < deg; i++) {
            int v = g_csr[off + i], k = i - 1;
            while (k >= 0 && g_csr[off + k] > v) { g_csr[off + k + 1] = g_csr[off + k]; k--; }
            g_csr[off + k + 1] = v;
        }
    }
}

// ---------------- prep: fold att vectors into tiny matrices (side stream) ----------
__global__ void k_prep(const float* __restrict__ Wn, const float* __restrict__ We,
                       const float* __restrict__ att) {
    int tid = threadIdx.x;
    if (tid < NDIM*NH) {
        int c = tid >> 2, h = tid & 3;
        float s0 = 0.f, s1 = 0.f;
        #pragma unroll
        for (int d = 0; d < DD; d++) {
            float w = Wn[c*GG + h*DD + d];
            s0 += w * att[h*(3*DD) + d];
            s1 += w * att[h*(3*DD) + DD + d];
        }
        g_Md[c*NH + h] = s0;
        g_Ms[c*NH + h] = s1;
    } else if (tid < NDIM*NH + EDIM*NH) {
        int k = tid - NDIM*NH;
        int c = k >> 2, h = k & 3;
        float s = 0.f;
        #pragma unroll
        for (int d = 0; d < DD; d++)
            s += We[c*GG + h*DD + d] * att[h*(3*DD) + 2*DD + d];
        g_Me[c*NH + h] = s;
    }
}

// ---------------- node score terms: sd/ss = x @ Md / Ms ----------------
__global__ void k_node(const float* __restrict__ xf) {
    int gn = blockIdx.x * blockDim.x + threadIdx.x;   // [0, BT*NNODE)
    if (gn >= BT*NNODE) return;
    const float* xp = xf + (size_t)gn * NDIM;
    float x[NDIM];
    #pragma unroll
    for (int c = 0; c < NDIM; c += 4) {
        float4 v = *reinterpret_cast<const float4*>(xp + c);
        x[c] = v.x; x[c+1] = v.y; x[c+2] = v.z; x[c+3] = v.w;
    }
    float sd[NH] = {0.f,0.f,0.f,0.f}, ss[NH] = {0.f,0.f,0.f,0.f};
    #pragma unroll
    for (int c = 0; c < NDIM; c++) {
        float4 md = *reinterpret_cast<const float4*>(&g_Md[c*NH]);
        float4 ms = *reinterpret_cast<const float4*>(&g_Ms[c*NH]);
        sd[0] = fmaf(x[c], md.x, sd[0]); sd[1] = fmaf(x[c], md.y, sd[1]);
        sd[2] = fmaf(x[c], md.z, sd[2]); sd[3] = fmaf(x[c], md.w, sd[3]);
        ss[0] = fmaf(x[c], ms.x, ss[0]); ss[1] = fmaf(x[c], ms.y, ss[1]);
        ss[2] = fmaf(x[c], ms.z, ss[2]); ss[3] = fmaf(x[c], ms.w, ss[3]);
    }
    *reinterpret_cast<float4*>(&g_sd[(size_t)gn*NH]) = make_float4(sd[0], sd[1], sd[2], sd[3]);
    *reinterpret_cast<float4*>(&g_ss[(size_t)gn*NH]) = make_float4(ss[0], ss[1], ss[2], ss[3]);
}

// ---------------- k_gat: fused softmax + x-space aggregation + proj + ELU + LN -------
__global__ void __launch_bounds__(256) k_gat(const float* __restrict__ xf,
                                             const float* __restrict__ efeat,
                                             const float* __restrict__ Wn,
                                             const float* __restrict__ We,
                                             const float* __restrict__ gamma,
                                             const float* __restrict__ beta) {
    __shared__ float s_al [8][32*4];
    __shared__ float s_ef [8][32*8];
    __shared__ int   s_src[8][32];
    __shared__ float s_axs[8][64];
    __shared__ float s_aef[8][32];

    int g    = blockIdx.y;
    int warp = threadIdx.x >> 5;
    int lane = threadIdx.x & 31;
    int node = blockIdx.x * 8 + warp;
    unsigned gE = (unsigned)g * NEDGE;
    unsigned gN = (unsigned)g * NNODE;
    const float* xg = xf + (size_t)gN * NDIM;
    const float* eg = efeat + (size_t)gE * EDIM;

    int off = g_off[node];
    int deg = g_off[node + 1] - off;
    float4 sd4 = *reinterpret_cast<const float4*>(&g_sd[(size_t)(gN + node)*NH]);

    int hA  = lane >> 4;
    int cA  = lane & 15;
    int hM  = lane >> 3;
    int cM  = lane & 7;
    float axs0 = 0.f, axs1 = 0.f, aef = 0.f;

    if (deg <= 32) {
        bool v = lane < deg;
        int e = 0, src = 0;
        float4 ea = make_float4(0.f,0.f,0.f,0.f), eb = ea, ss4 = ea;
        if (v) {
            e = g_csr[off + lane];
            src = g_src[e];
            const float* ef = eg + e*EDIM;
            ea = *reinterpret_cast<const float4*>(ef);
            eb = *reinterpret_cast<const float4*>(ef + 4);
            ss4 = *reinterpret_cast<const float4*>(&g_ss[(size_t)(gN + src)*NH]);
        }
        float efv[8] = {ea.x, ea.y, ea.z, ea.w, eb.x, eb.y, eb.z, eb.w};
        float s0 = sd4.x + ss4.x, s1 = sd4.y + ss4.y;
        float s2 = sd4.z + ss4.z, s3 = sd4.w + ss4.w;
        #pragma unroll
        for (int c = 0; c < EDIM; c++) {
            float4 me = *reinterpret_cast<const float4*>(&g_Me[c*NH]);
            s0 = fmaf(efv[c], me.x, s0);
            s1 = fmaf(efv[c], me.y, s1);
            s2 = fmaf(efv[c], me.z, s2);
            s3 = fmaf(efv[c], me.w, s3);
        }
        s0 = (s0 > 0.f) ? s0 : 0.2f*s0;  s1 = (s1 > 0.f) ? s1 : 0.2f*s1;
        s2 = (s2 > 0.f) ? s2 : 0.2f*s2;  s3 = (s3 > 0.f) ? s3 : 0.2f*s3;
        if (!v) { s0 = s1 = s2 = s3 = -1e30f; }
        float m0 = s0, m1 = s1, m2 = s2, m3 = s3;
        #pragma unroll
        for (int o = 16; o; o >>= 1) {
            m0 = fmaxf(m0, __shfl_xor_sync(0xFFFFFFFFu, m0, o));
            m1 = fmaxf(m1, __shfl_xor_sync(0xFFFFFFFFu, m1, o));
            m2 = fmaxf(m2, __shfl_xor_sync(0xFFFFFFFFu, m2, o));
            m3 = fmaxf(m3, __shfl_xor_sync(0xFFFFFFFFu, m3, o));
        }
        float e0 = v ? __expf(s0 - m0) : 0.f;
        float e1 = v ? __expf(s1 - m1) : 0.f;
        float e2 = v ? __expf(s2 - m2) : 0.f;
        float e3 = v ? __expf(s3 - m3) : 0.f;
        float t0 = e0, t1 = e1, t2 = e2, t3 = e3;
        #pragma unroll
        for (int o = 16; o; o >>= 1) {
            t0 += __shfl_xor_sync(0xFFFFFFFFu, t0, o);
            t1 += __shfl_xor_sync(0xFFFFFFFFu, t1, o);
            t2 += __shfl_xor_sync(0xFFFFFFFFu, t2, o);
            t3 += __shfl_xor_sync(0xFFFFFFFFu, t3, o);
        }
        if (v) {
            float4 al = make_float4(e0/(t0 + 1e-16f), e1/(t1 + 1e-16f),
                                    e2/(t2 + 1e-16f), e3/(t3 + 1e-16f));
            *reinterpret_cast<float4*>(&g_score[(size_t)(gE + e)*NH]) = al;
            s_src[warp][lane] = src;
            *reinterpret_cast<float4*>(&s_al[warp][lane*4]) = al;
            *reinterpret_cast<float4*>(&s_ef[warp][lane*8])     = ea;
            *reinterpret_cast<float4*>(&s_ef[warp][lane*8 + 4]) = eb;
        }
        __syncwarp();
        for (int i = 0; i < deg; i++) {
            int s = s_src[warp][i];
            float a_lo = s_al[warp][i*4 + hA];
            float a_hi = s_al[warp][i*4 + 2 + hA];
            float xv = __ldg(&xg[s*NDIM + cA]);
            axs0 = fmaf(a_lo, xv, axs0);
            axs1 = fmaf(a_hi, xv, axs1);
            aef  = fmaf(s_al[warp][i*4 + hM], s_ef[warp][i*8 + cM], aef);
        }
    } else {
        float m0 = -1e30f, m1 = -1e30f, m2 = -1e30f, m3 = -1e30f;
        for (int i = lane; i < deg; i += 32) {
            int e = g_csr[off + i];
            const float* ef = eg + e*EDIM;
            float4 ea = *reinterpret_cast<const float4*>(ef);
            float4 eb = *reinterpret_cast<const float4*>(ef + 4);
            float efv[8] = {ea.x, ea.y, ea.z, ea.w, eb.x, eb.y, eb.z, eb.w};
            float4 ss4 = *reinterpret_cast<const float4*>(&g_ss[(size_t)(gN + g_src[e])*NH]);
            float s0 = sd4.x + ss4.x, s1 = sd4.y + ss4.y;
            float s2 = sd4.z + ss4.z, s3 = sd4.w + ss4.w;
            #pragma unroll
            for (int c = 0; c < EDIM; c++) {
                float4 me = *reinterpret_cast<const float4*>(&g_Me[c*NH]);
                s0 = fmaf(efv[c], me.x, s0);
                s1 = fmaf(efv[c], me.y, s1);
                s2 = fmaf(efv[c], me.z, s2);
                s3 = fmaf(efv[c], me.w, s3);
            }
            s0 = (s0 > 0.f) ? s0 : 0.2f*s0;  s1 = (s1 > 0.f) ? s1 : 0.2f*s1;
            s2 = (s2 > 0.f) ? s2 : 0.2f*s2;  s3 = (s3 > 0.f) ? s3 : 0.2f*s3;
            *reinterpret_cast<float4*>(&g_score[(size_t)(gE + e)*NH]) = make_float4(s0, s1, s2, s3);
            m0 = fmaxf(m0, s0); m1 = fmaxf(m1, s1);
            m2 = fmaxf(m2, s2); m3 = fmaxf(m3, s3);
        }
        #pragma unroll
        for (int o = 16; o; o >>= 1) {
            m0 = fmaxf(m0, __shfl_xor_sync(0xFFFFFFFFu, m0, o));
            m1 = fmaxf(m1, __shfl_xor_sync(0xFFFFFFFFu, m1, o));
            m2 = fmaxf(m2, __shfl_xor_sync(0xFFFFFFFFu, m2, o));
            m3 = fmaxf(m3, __shfl_xor_sync(0xFFFFFFFFu, m3, o));
        }
        float t0 = 0.f, t1 = 0.f, t2 = 0.f, t3 = 0.f;
        for (int i = lane; i < deg; i += 32) {
            int e = g_csr[off + i];
            float4 sc = *reinterpret_cast<const float4*>(&g_score[(size_t)(gE + e)*NH]);
            float e0 = __expf(sc.x - m0), e1 = __expf(sc.y - m1);
            float e2 = __expf(sc.z - m2), e3 = __expf(sc.w - m3);
            *reinterpret_cast<float4*>(&g_score[(size_t)(gE + e)*NH]) = make_float4(e0, e1, e2, e3);
            t0 += e0; t1 += e1; t2 += e2; t3 += e3;
        }
        #pragma unroll
        for (int o = 16; o; o >>= 1) {
            t0 += __shfl_xor_sync(0xFFFFFFFFu, t0, o);
            t1 += __shfl_xor_sync(0xFFFFFFFFu, t1, o);
            t2 += __shfl_xor_sync(0xFFFFFFFFu, t2, o);
            t3 += __shfl_xor_sync(0xFFFFFFFFu, t3, o);
        }
        float r0 = 1.f/(t0 + 1e-16f), r1 = 1.f/(t1 + 1e-16f);
        float r2 = 1.f/(t2 + 1e-16f), r3 = 1.f/(t3 + 1e-16f);
        for (int i = lane; i < deg; i += 32) {
            int e = g_csr[off + i];
            float4 es = *reinterpret_cast<const float4*>(&g_score[(size_t)(gE + e)*NH]);
            *reinterpret_cast<float4*>(&g_score[(size_t)(gE + e)*NH]) =
                make_float4(es.x*r0, es.y*r1, es.z*r2, es.w*r3);
        }
        __threadfence();
        __syncwarp();
        for (int i = 0; i < deg; i++) {
            int e = g_csr[off + i];
            int s = __ldg(&g_src[e]);
            const float* ap = &g_score[(size_t)(gE + e)*NH];
            float a_lo = __ldg(ap + hA);
            float a_hi = __ldg(ap + 2 + hA);
            float a_me = __ldg(ap + hM);
            float xv   = __ldg(&xg[s*NDIM + cA]);
            float ev   = __ldg(&eg[e*EDIM + cM]);
            axs0 = fmaf(a_lo, xv, axs0);
            axs1 = fmaf(a_hi, xv, axs1);
            aef  = fmaf(a_me, ev, aef);
        }
    }

    s_axs[warp][hA*16 + cA]       = axs0;
    s_axs[warp][(2 + hA)*16 + cA] = axs1;
    s_aef[warp][lane] = aef;
    __syncwarp();

    float o01[2];
    #pragma unroll
    for (int half = 0; half < 2; half++) {
        int j = lane + half*32;
        int h = j >> 4;
        float acc = 0.f;
        #pragma unroll
        for (int c = 0; c < NDIM; c++)
            acc = fmaf(s_axs[warp][h*16 + c], __ldg(&Wn[c*GG + j]), acc);
        #pragma unroll
        for (int c = 0; c < EDIM; c++)
            acc = fmaf(s_aef[warp][h*8 + c], __ldg(&We[c*GG + j]), acc);
        o01[half] = (acc > 0.f) ? acc : (__expf(acc) - 1.f);
    }
    float s = o01[0] + o01[1];
    float q = o01[0]*o01[0] + o01[1]*o01[1];
    #pragma unroll
    for (int o = 16; o; o >>= 1) {
        s += __shfl_xor_sync(0xFFFFFFFFu, s, o);
        q += __shfl_xor_sync(0xFFFFFFFFu, q, o);
    }
    float mu = s * (1.f/GG);
    float inv = rsqrtf(q * (1.f/GG) - mu*mu + 1e-5f);
    int b = g / TT, t = g - b*TT;
    size_t gb = (((size_t)b*NNODE + node)*TT + t)*GG;
    g_gin[gb + lane]      = (o01[0] - mu)*inv*__ldg(&gamma[lane])      + __ldg(&beta[lane]);
    g_gin[gb + lane + 32] = (o01[1] - mu)*inv*__ldg(&gamma[lane + 32]) + __ldg(&beta[lane + 32]);
}

// ---------------- attention output ----------------
__global__ void k_attn(float* __restrict__ out3) {
    int te = blockIdx.x * blockDim.x + threadIdx.x;
    if (te >= TT*NEDGE) return;
    int e = te % NEDGE;
    int t = te / NEDGE;
    float4 s = make_float4(0.f, 0.f, 0.f, 0.f);
    #pragma unroll
    for (int b = 0; b < BB; b++) {
        float4 v = *reinterpret_cast<const float4*>(
            &g_score[(((size_t)(b*TT + t))*NEDGE + e)*NH]);
        s.x += v.x; s.y += v.y; s.z += v.z; s.w += v.w;
    }
    s.x *= 0.25f; s.y *= 0.25f; s.z *= 0.25f; s.w *= 0.25f;
    *reinterpret_cast<float4*>(&out3[(size_t)te*NH]) = s;
}

// ---------------- gi GEMM: gate-split 64x64, 4r x 4c/thread (R9/R14 config) ---------
__global__ void __launch_bounds__(256) k_gi(const float* __restrict__ Wih,
                                            const float* __restrict__ bih) {
    __shared__ float Ws[64*64];      // Ws[k*64+o]
    __shared__ float X [64*68];      // X[r*68+k]
    int tid = threadIdx.x;
    int sgate = blockIdx.y;          // 0..2
    for (int i = tid; i < 64*64; i += 256) {
        int o = i >> 6, k = i & 63;
        Ws[k*64 + o] = Wih[(size_t)(sgate*64 + o)*64 + k];
    }
    size_t row0 = (size_t)blockIdx.x * 64;
    for (int i = tid; i < 64*64; i += 256) {
        int r = i >> 6, k = i & 63;
        X[r*68 + k] = g_gin[row0*GG + i];
    }
    __syncthreads();
    int tx = tid & 15;               // cols tx*4..+4
    int ty = tid >> 4;               // rows ty*4..+4
    float acc[4][4];
    #pragma unroll
    for (int r = 0; r < 4; r++)
        #pragma unroll
        for (int c = 0; c < 4; c++) acc[r][c] = 0.f;
    #pragma unroll 4
    for (int k = 0; k < 64; k += 4) {
        float4 w0 = *reinterpret_cast<float4*>(&Ws[(k+0)*64 + tx*4]);
        float4 w1 = *reinterpret_cast<float4*>(&Ws[(k+1)*64 + tx*4]);
        float4 w2 = *reinterpret_cast<float4*>(&Ws[(k+2)*64 + tx*4]);
        float4 w3 = *reinterpret_cast<float4*>(&Ws[(k+3)*64 + tx*4]);
        #pragma unroll
        for (int r = 0; r < 4; r++) {
            float4 xv = *reinterpret_cast<float4*>(&X[(ty*4 + r)*68 + k]);
            acc[r][0] = fmaf(xv.x, w0.x, acc[r][0]);
            acc[r][1] = fmaf(xv.x, w0.y, acc[r][1]);
            acc[r][2] = fmaf(xv.x, w0.z, acc[r][2]);
            acc[r][3] = fmaf(xv.x, w0.w, acc[r][3]);
            acc[r][0] = fmaf(xv.y, w1.x, acc[r][0]);
            acc[r][1] = fmaf(xv.y, w1.y, acc[r][1]);
            acc[r][2] = fmaf(xv.y, w1.z, acc[r][2]);
            acc[r][3] = fmaf(xv.y, w1.w, acc[r][3]);
            acc[r][0] = fmaf(xv.z, w2.x, acc[r][0]);
            acc[r][1] = fmaf(xv.z, w2.y, acc[r][1]);
            acc[r][2] = fmaf(xv.z, w2.z, acc[r][2]);
            acc[r][3] = fmaf(xv.z, w2.w, acc[r][3]);
            acc[r][0] = fmaf(xv.w, w3.x, acc[r][0]);
            acc[r][1] = fmaf(xv.w, w3.y, acc[r][1]);
            acc[r][2] = fmaf(xv.w, w3.z, acc[r][2]);
            acc[r][3] = fmaf(xv.w, w3.w, acc[r][3]);
        }
    }
    float4 bv = *reinterpret_cast<const float4*>(&bih[sgate*64 + tx*4]);
    #pragma unroll
    for (int r = 0; r < 4; r++) {
        size_t base = (row0 + ty*4 + r) * 192 + sgate*64 + tx*4;
        *reinterpret_cast<float4*>(&g_gi[base]) =
            make_float4(acc[r][0] + bv.x, acc[r][1] + bv.y,
                        acc[r][2] + bv.z, acc[r][3] + bv.w);
    }
}

// ---------------- fused GRU: 16 nodes/block (500 blocks), 4 nodes/thread ------------
// + L2 prefetch of this step's gi rows before the k-loop (hides LDG latency)
#define HP 20
__global__ void k_gru(const float* __restrict__ Whh, const float* __restrict__ bhh_g,
                      const float* __restrict__ Wout, const float* __restrict__ bout,
                      float* __restrict__ out) {
    extern __shared__ float sm[];
    float* Wt  = sm;                      // [64][192]
    float* h0s = Wt + 64*192;             // [64][HP]
    float* h1s = h0s + 64*HP;             // [64][HP]
    float* bs  = h1s + 64*HP;             // [192]
    float* pp  = bs + 192;                // [16][2]
    int tid = threadIdx.x;
    for (int i = tid; i < 192*64; i += 256) {
        int o = i >> 6, k = i & 63;
        Wt[k*192 + o] = Whh[i];
    }
    for (int i = tid; i < 192; i += 256) bs[i] = bhh_g[i];
    __syncthreads();

    int j  = tid & 63;
    int ng = tid >> 6;                    // 0..3, owns 4 nodes
    int node0 = blockIdx.x * 16;
    float b_r = bs[j], b_z = bs[j + 64], b_n = bs[j + 128];

    const float* gp[4];
    #pragma unroll
    for (int i = 0; i < 4; i++)
        gp[i] = g_gi + (size_t)(node0 + ng*4 + i) * (TT*192);

    float h[4];
    #pragma unroll
    for (int i = 0; i < 4; i++) {
        float gr = __ldg(gp[i] + j), gz = __ldg(gp[i] + 64 + j), gn = __ldg(gp[i] + 128 + j);
        float r = 1.f/(1.f + __expf(-(gr + b_r)));
        float z = 1.f/(1.f + __expf(-(gz + b_z)));
        float n = tanhf(gn + r*b_n);
        h[i] = (1.f - z)*n;
    }
    #pragma unroll
    for (int i = 0; i < 4; i++) h0s[j*HP + ng*4 + i] = h[i];
    __syncthreads();

    for (int t = 1; t < TT; t++) {
        // prefetch this step's gi lines into L2 before the long k-loop
        #pragma unroll
        for (int i = 0; i < 4; i++) {
            const float* p0 = gp[i] + t*192 + j;
            asm volatile("prefetch.global.L2 [%0];" :: "l"(p0));
            asm volatile("prefetch.global.L2 [%0];" :: "l"(p0 + 64));
            asm volatile("prefetch.global.L2 [%0];" :: "l"(p0 + 128));
        }
        float* hin  = ((t - 1) & 1) ? h1s : h0s;
        float* hout = (t & 1) ? h1s : h0s;
        float ar[4], az[4], an[4];
        #pragma unroll
        for (int i = 0; i < 4; i++) { ar[i] = 0.f; az[i] = 0.f; an[i] = 0.f; }
        #pragma unroll 4
        for (int k = 0; k < 64; k++) {
            float w0 = Wt[k*192 + j];
            float w1 = Wt[k*192 + 64 + j];
            float w2 = Wt[k*192 + 128 + j];
            float4 hv = *reinterpret_cast<float4*>(&hin[k*HP + ng*4]);
            float hvv[4] = {hv.x, hv.y, hv.z, hv.w};
            #pragma unroll
            for (int i = 0; i < 4; i++) {
                ar[i] = fmaf(hvv[i], w0, ar[i]);
                az[i] = fmaf(hvv[i], w1, az[i]);
                an[i] = fmaf(hvv[i], w2, an[i]);
            }
        }
        #pragma unroll
        for (int i = 0; i < 4; i++) {
            float gr = __ldg(gp[i] + t*192 + j);
            float gz = __ldg(gp[i] + t*192 + 64 + j);
            float gn = __ldg(gp[i] + t*192 + 128 + j);
            float r = 1.f/(1.f + __expf(-(gr + ar[i] + b_r)));
            float z = 1.f/(1.f + __expf(-(gz + az[i] + b_z)));
            float n = tanhf(gn + r*(an[i] + b_n));
            h[i] = (1.f - z)*n + z*h[i];
        }
        #pragma unroll
        for (int i = 0; i < 4; i++) hout[j*HP + ng*4 + i] = h[i];
        __syncthreads();
    }

    #pragma unroll
    for (int i = 0; i < 4; i++)
        out[8000 + (size_t)(node0 + ng*4 + i)*GHH + j] = h[i];
    float wj = __ldg(&Wout[j]);
    int half = (j >> 5);
    #pragma unroll
    for (int i = 0; i < 4; i++) {
        float p = h[i] * wj;
        #pragma unroll
        for (int o = 16; o; o >>= 1) p += __shfl_xor_sync(0xFFFFFFFFu, p, o);
        if ((j & 31) == 0) pp[(ng*4 + i)*2 + half] = p;
    }
    __syncthreads();
    if (tid < 16)
        out[node0 + tid] = pp[tid*2] + pp[tid*2 + 1] + __ldg(&bout[0]);
}

// ---------------- launch: R14 fork-join two-stream graph -----------------------------
extern "C" void kernel_launch(void* const* d_in, const int* in_sizes, int n_in,
                              void* d_out, int out_size) {
    const float* node_features = (const float*)d_in[0];
    const float* edge_features = (const float*)d_in[1];
    const float* W_node  = (const float*)d_in[2];
    const float* W_edge  = (const float*)d_in[3];
    const float* att     = (const float*)d_in[4];
    const float* ln_gamma= (const float*)d_in[5];
    const float* ln_beta = (const float*)d_in[6];
    const float* W_ih    = (const float*)d_in[7];
    const float* W_hh    = (const float*)d_in[8];
    const float* b_ih    = (const float*)d_in[9];
    const float* b_hh    = (const float*)d_in[10];
    const float* W_out   = (const float*)d_in[11];
    const float* b_out   = (const float*)d_in[12];
    const int*   edge_index = (const int*)d_in[13];   // int32 (JAX x64 off)
    float* out = (float*)d_out;

    static cudaStream_t sB = nullptr;
    static cudaEvent_t evStart, evNode, evGat, evAttn;
    static int inited = 0;
    if (!inited) {
        cudaStreamCreateWithFlags(&sB, cudaStreamNonBlocking);
        cudaEventCreateWithFlags(&evStart, cudaEventDisableTiming);
        cudaEventCreateWithFlags(&evNode,  cudaEventDisableTiming);
        cudaEventCreateWithFlags(&evGat,   cudaEventDisableTiming);
        cudaEventCreateWithFlags(&evAttn,  cudaEventDisableTiming);
        cudaFuncSetAttribute(k_gru, cudaFuncAttributeMaxDynamicSharedMemorySize,
                             (64*192 + 2*64*HP + 192 + 32) * 4);
        inited = 1;
    }
    int gru_smem = (64*192 + 2*64*HP + 192 + 32) * 4;

    // fork point
    cudaEventRecord(evStart, 0);
    cudaStreamWaitEvent(sB, evStart, 0);

    // main stream: CSR chain (indices 0..3; sortB profiled at idx 3)
    k_count<<<(NEDGE + 255)/256, 256>>>(edge_index);                  // 0
    k_scan <<<1, 1024>>>();                                           // 1
    k_fillA<<<(NEDGE + 255)/256, 256>>>();                            // 2
    k_sortB<<<(NNODE*32 + 255)/256, 256>>>();                         // 3 <- profiled

    // side stream: prep + node (independent of CSR)
    k_prep<<<1, 128, 0, sB>>>(W_node, W_edge, att);                   // 4
    k_node<<<(BT*NNODE + 255)/256, 256, 0, sB>>>(node_features);      // 5
    cudaEventRecord(evNode, sB);

    // main: gat after CSR + node
    cudaStreamWaitEvent(0, evNode, 0);
    dim3 ggrid(NNODE/8, BT);
    k_gat<<<ggrid, 256>>>(node_features, edge_features, W_node, W_edge,
                          ln_gamma, ln_beta);                         // 6
    cudaEventRecord(evGat, 0);

    // main: gi -> gru
    dim3 gigrid(BB*NNODE*TT/64, 3);
    k_gi <<<gigrid, 256>>>(W_ih, b_ih);                               // 7
    k_gru<<<(BB*NNODE)/16, 256, gru_smem>>>(W_hh, b_hh, W_out, b_out, out); // 8

    // side: attn concurrent with gi/gru (depends only on gat)
    cudaStreamWaitEvent(sB, evGat, 0);
    k_attn<<<(TT*NEDGE + 255)/256, 256, 0, sB>>>(out + 8000 + (size_t)BB*NNODE*GHH); // 9
    cudaEventRecord(evAttn, sB);

    // join
    cudaStreamWaitEvent(0, evAttn, 0);
}